// round 1
// baseline (speedup 1.0000x reference)
#include <cuda_runtime.h>
#include <math.h>

#define NN 100000
#define EE 1600000
#define DIN 128
#define DH 128
#define DOUT 64
#define NCHUNK 98   // ceil(NN/1024)

// ---------------- scratch (device globals; no allocation allowed) ----------------
__device__ float g_agg[(size_t)NN * DH];   // aggregated (mean) features, scaled
__device__ float g_h1[(size_t)NN * DH];
__device__ float g_h2[(size_t)NN * DH];
__device__ float g_h3[(size_t)NN * DOUT];
__device__ float g_deginv[NN];
__device__ int   g_cnt[NN];
__device__ int   g_rowptr[NN];
__device__ int   g_cursor[NN];
__device__ int   g_col[EE];
__device__ int   g_bsum[128];

// ---------------- CSR build ----------------
__global__ void zero_cnt_kernel() {
    int i = blockIdx.x * blockDim.x + threadIdx.x;
    if (i < NN) g_cnt[i] = 0;
}

__global__ void hist_kernel(const int* __restrict__ ei) {
    int e = blockIdx.x * blockDim.x + threadIdx.x;
    if (e < EE) atomicAdd(&g_cnt[ei[EE + e]], 1);
}

// per-1024-chunk sums
__global__ void bsum_kernel() {
    __shared__ int sm[256];
    int b = blockIdx.x, t = threadIdx.x;
    int base = b * 1024 + t * 4;
    int s = 0;
#pragma unroll
    for (int i = 0; i < 4; i++) {
        int n = base + i;
        if (n < NN) s += g_cnt[n];
    }
    sm[t] = s;
    __syncthreads();
    for (int off = 128; off > 0; off >>= 1) {
        if (t < off) sm[t] += sm[t + off];
        __syncthreads();
    }
    if (t == 0) g_bsum[b] = sm[0];
}

// exclusive scan of the chunk sums (single block)
__global__ void scan_bsum_kernel() {
    __shared__ int sm[128];
    int t = threadIdx.x;
    int v = (t < NCHUNK) ? g_bsum[t] : 0;
    sm[t] = v;
    __syncthreads();
    for (int off = 1; off < 128; off <<= 1) {
        int add = (t >= off) ? sm[t - off] : 0;
        __syncthreads();
        sm[t] += add;
        __syncthreads();
    }
    if (t < NCHUNK) g_bsum[t] = sm[t] - v;  // exclusive
}

// rowptr / cursor / deginv emission (local exclusive scan + chunk offset)
__global__ void emit_kernel() {
    __shared__ int sm[256];
    int b = blockIdx.x, t = threadIdx.x;
    int n0 = b * 1024 + t * 4;
    int c[4];
    int tsum = 0;
#pragma unroll
    for (int i = 0; i < 4; i++) {
        c[i] = (n0 + i < NN) ? g_cnt[n0 + i] : 0;
        tsum += c[i];
    }
    sm[t] = tsum;
    __syncthreads();
    for (int off = 1; off < 256; off <<= 1) {
        int add = (t >= off) ? sm[t - off] : 0;
        __syncthreads();
        sm[t] += add;
        __syncthreads();
    }
    int base = g_bsum[b] + sm[t] - tsum;  // exclusive position of first element
#pragma unroll
    for (int i = 0; i < 4; i++) {
        int n = n0 + i;
        if (n < NN) {
            g_rowptr[n] = base;
            g_cursor[n] = base;
            g_deginv[n] = 1.0f / (float)max(c[i], 1);
            base += c[i];
        }
    }
}

__global__ void fill_kernel(const int* __restrict__ ei) {
    int e = blockIdx.x * blockDim.x + threadIdx.x;
    if (e < EE) {
        int d = ei[EE + e];
        int pos = atomicAdd(&g_cursor[d], 1);
        g_col[pos] = ei[e];
    }
}

// ---------------- aggregation: one warp per node ----------------
__global__ void agg_kernel(const float* __restrict__ hin) {
    int warp = (blockIdx.x * blockDim.x + threadIdx.x) >> 5;
    int lane = threadIdx.x & 31;
    if (warp >= NN) return;
    int start = g_rowptr[warp];
    int cnt = g_cnt[warp];
    float ax = 0.f, ay = 0.f, az = 0.f, aw = 0.f;
    int j = 0;
    while (j < cnt) {
        int batch = min(cnt - j, 32);
        int s = (lane < batch) ? g_col[start + j + lane] : 0;
        for (int t = 0; t < batch; t++) {
            int sv = __shfl_sync(0xffffffffu, s, t);
            float4 v = *(const float4*)&hin[(size_t)sv * DH + lane * 4];
            ax += v.x; ay += v.y; az += v.z; aw += v.w;
        }
        j += batch;
    }
    float sc = g_deginv[warp];
    float4 o = make_float4(ax * sc, ay * sc, az * sc, aw * sc);
    *(float4*)&g_agg[(size_t)warp * DH + lane * 4] = o;
}

// ---------------- fused dual-SGEMM: out = relu?(agg@Wl + A2@Wr + b) ----------------
// BM=64, BK=32, thread tile 8x4. BN = output width (128 or 64).
template <int BN>
__global__ void __launch_bounds__((BN / 4) * 8) gemm_kernel(
    const float* __restrict__ A2, const float* __restrict__ Wl,
    const float* __restrict__ Wr, const float* __restrict__ bias,
    float* __restrict__ out, int doRelu) {
    constexpr int BM = 64, BK = 32;
    constexpr int TCOLS = BN / 4;
    constexpr int THREADS = TCOLS * 8;
    __shared__ float As[BK][BM + 4];  // transposed, padded (16B-aligned rows of 8)
    __shared__ float Ws[BK][BN];

    const int tid = threadIdx.x;
    const int c = tid % TCOLS;   // feature quad
    const int r = tid / TCOLS;   // node octet
    const int m_base = blockIdx.x * BM;

    float acc[8][4];
#pragma unroll
    for (int i = 0; i < 8; i++)
#pragma unroll
        for (int j = 0; j < 4; j++) acc[i][j] = 0.f;

    for (int kc = 0; kc < 2 * DH; kc += BK) {
        const float* A = (kc < DH) ? g_agg : A2;
        const float* W = (kc < DH) ? Wl : Wr;
        const int k0 = kc & (DH - 1);

        // stage A tile (transposed) — coalesced float4 reads along k
#pragma unroll
        for (int v = tid; v < BM * BK / 4; v += THREADS) {
            int m = v >> 3;          // BK/4 = 8 quads per node row
            int kq = v & 7;
            int node = m_base + m;
            float4 a = make_float4(0.f, 0.f, 0.f, 0.f);
            if (node < NN) a = *(const float4*)&A[(size_t)node * DH + k0 + kq * 4];
            As[kq * 4 + 0][m] = a.x;
            As[kq * 4 + 1][m] = a.y;
            As[kq * 4 + 2][m] = a.z;
            As[kq * 4 + 3][m] = a.w;
        }
        // stage W tile (same layout)
#pragma unroll
        for (int v = tid; v < BK * BN / 4; v += THREADS) {
            int k = v / (BN / 4);
            int fq = v % (BN / 4);
            *(float4*)&Ws[k][fq * 4] =
                *(const float4*)&W[(size_t)(k0 + k) * BN + fq * 4];
        }
        __syncthreads();

#pragma unroll
        for (int k = 0; k < BK; k++) {
            float4 w = *(const float4*)&Ws[k][c * 4];
            const float* ap = &As[k][r * 8];
            float4 alo = *(const float4*)ap;
            float4 ahi = *(const float4*)(ap + 4);
            float a[8] = {alo.x, alo.y, alo.z, alo.w, ahi.x, ahi.y, ahi.z, ahi.w};
            float wv[4] = {w.x, w.y, w.z, w.w};
#pragma unroll
            for (int i = 0; i < 8; i++)
#pragma unroll
                for (int j = 0; j < 4; j++) acc[i][j] += a[i] * wv[j];
        }
        __syncthreads();
    }

    float4 b4 = *(const float4*)&bias[c * 4];
    float bv[4] = {b4.x, b4.y, b4.z, b4.w};
#pragma unroll
    for (int i = 0; i < 8; i++) {
        int node = m_base + r * 8 + i;
        if (node < NN) {
            float o[4];
#pragma unroll
            for (int j = 0; j < 4; j++) {
                float t = acc[i][j] + bv[j];
                o[j] = doRelu ? fmaxf(t, 0.f) : t;
            }
            *(float4*)&out[(size_t)node * BN + c * 4] =
                make_float4(o[0], o[1], o[2], o[3]);
        }
    }
}

// ---------------- L2 normalize (one warp per node) ----------------
__global__ void norm_kernel(const float* __restrict__ h, float* __restrict__ out) {
    int warp = (blockIdx.x * blockDim.x + threadIdx.x) >> 5;
    int lane = threadIdx.x & 31;
    if (warp >= NN) return;
    float v0 = h[(size_t)warp * DOUT + lane];
    float v1 = h[(size_t)warp * DOUT + 32 + lane];
    float ss = v0 * v0 + v1 * v1;
#pragma unroll
    for (int off = 16; off > 0; off >>= 1) ss += __shfl_xor_sync(0xffffffffu, ss, off);
    float inv = 1.0f / fmaxf(sqrtf(ss), 1e-12f);
    out[(size_t)warp * DOUT + lane] = v0 * inv;
    out[(size_t)warp * DOUT + 32 + lane] = v1 * inv;
}

// ---------------- launch ----------------
extern "C" void kernel_launch(void* const* d_in, const int* in_sizes, int n_in,
                              void* d_out, int out_size) {
    const float* x   = (const float*)d_in[0];
    const int*   ei  = (const int*)d_in[1];
    const float* Wl1 = (const float*)d_in[2];
    const float* bl1 = (const float*)d_in[3];
    const float* Wr1 = (const float*)d_in[4];
    const float* Wl2 = (const float*)d_in[5];
    const float* bl2 = (const float*)d_in[6];
    const float* Wr2 = (const float*)d_in[7];
    const float* Wl3 = (const float*)d_in[8];
    const float* bl3 = (const float*)d_in[9];
    const float* Wr3 = (const float*)d_in[10];
    float* out = (float*)d_out;

    void *p1, *p2, *p3;
    cudaGetSymbolAddress(&p1, g_h1);
    cudaGetSymbolAddress(&p2, g_h2);
    cudaGetSymbolAddress(&p3, g_h3);
    float* h1 = (float*)p1;
    float* h2 = (float*)p2;
    float* h3 = (float*)p3;

    // CSR build (rebuilt every call; deterministic work)
    zero_cnt_kernel<<<(NN + 255) / 256, 256>>>();
    hist_kernel<<<(EE + 255) / 256, 256>>>(ei);
    bsum_kernel<<<NCHUNK, 256>>>();
    scan_bsum_kernel<<<1, 128>>>();
    emit_kernel<<<NCHUNK, 256>>>();
    fill_kernel<<<(EE + 255) / 256, 256>>>(ei);

    const int AGG_BLOCKS = (NN + 7) / 8;      // 8 warps (nodes) per 256-thread block
    const int GEMM_BLOCKS = (NN + 63) / 64;

    // layer 1
    agg_kernel<<<AGG_BLOCKS, 256>>>(x);
    gemm_kernel<128><<<GEMM_BLOCKS, 256>>>(x, Wl1, Wr1, bl1, h1, 1);
    // layer 2
    agg_kernel<<<AGG_BLOCKS, 256>>>(h1);
    gemm_kernel<128><<<GEMM_BLOCKS, 256>>>(h1, Wl2, Wr2, bl2, h2, 1);
    // layer 3
    agg_kernel<<<AGG_BLOCKS, 256>>>(h2);
    gemm_kernel<64><<<GEMM_BLOCKS, 128>>>(h2, Wl3, Wr3, bl3, h3, 0);
    // L2 normalize
    norm_kernel<<<(NN + 7) / 8, 256>>>(h3, out);
}

// round 2
// speedup vs baseline: 1.2198x; 1.2198x over previous
#include <cuda_runtime.h>
#include <math.h>
#include <stdint.h>

#define NN 100000
#define EE 1600000
#define DH 128
#define DOUT 64
#define NCHUNK 98   // ceil(NN/1024)

// ---------------- scratch (device globals) ----------------
__device__ float g_tl[(size_t)NN * DH];    // Y = H @ Wl (to be aggregated)
__device__ float g_tr[(size_t)NN * DH];    // Y = H @ Wr (self term)
__device__ float g_h1[(size_t)NN * DH];
__device__ float g_h2[(size_t)NN * DH];
__device__ float g_deginv[NN];
__device__ int   g_cnt[NN];
__device__ int   g_rowptr[NN];
__device__ int   g_cursor[NN];
__device__ int   g_col[EE];
__device__ int   g_bsum[128];

// ---------------- CSR build ----------------
__global__ void zero_cnt_kernel() {
    int i = blockIdx.x * blockDim.x + threadIdx.x;
    if (i < NN) g_cnt[i] = 0;
}

__global__ void hist_kernel(const int* __restrict__ ei) {
    int e = blockIdx.x * blockDim.x + threadIdx.x;
    if (e < EE) atomicAdd(&g_cnt[ei[EE + e]], 1);
}

__global__ void bsum_kernel() {
    __shared__ int sm[256];
    int b = blockIdx.x, t = threadIdx.x;
    int base = b * 1024 + t * 4;
    int s = 0;
#pragma unroll
    for (int i = 0; i < 4; i++) {
        int n = base + i;
        if (n < NN) s += g_cnt[n];
    }
    sm[t] = s;
    __syncthreads();
    for (int off = 128; off > 0; off >>= 1) {
        if (t < off) sm[t] += sm[t + off];
        __syncthreads();
    }
    if (t == 0) g_bsum[b] = sm[0];
}

__global__ void scan_bsum_kernel() {
    __shared__ int sm[128];
    int t = threadIdx.x;
    int v = (t < NCHUNK) ? g_bsum[t] : 0;
    sm[t] = v;
    __syncthreads();
    for (int off = 1; off < 128; off <<= 1) {
        int add = (t >= off) ? sm[t - off] : 0;
        __syncthreads();
        sm[t] += add;
        __syncthreads();
    }
    if (t < NCHUNK) g_bsum[t] = sm[t] - v;  // exclusive
}

__global__ void emit_kernel() {
    __shared__ int sm[256];
    int b = blockIdx.x, t = threadIdx.x;
    int n0 = b * 1024 + t * 4;
    int c[4];
    int tsum = 0;
#pragma unroll
    for (int i = 0; i < 4; i++) {
        c[i] = (n0 + i < NN) ? g_cnt[n0 + i] : 0;
        tsum += c[i];
    }
    sm[t] = tsum;
    __syncthreads();
    for (int off = 1; off < 256; off <<= 1) {
        int add = (t >= off) ? sm[t - off] : 0;
        __syncthreads();
        sm[t] += add;
        __syncthreads();
    }
    int base = g_bsum[b] + sm[t] - tsum;
#pragma unroll
    for (int i = 0; i < 4; i++) {
        int n = n0 + i;
        if (n < NN) {
            g_rowptr[n] = base;
            g_cursor[n] = base;
            g_deginv[n] = 1.0f / (float)max(c[i], 1);
            base += c[i];
        }
    }
}

__global__ void fill_kernel(const int* __restrict__ ei) {
    int e = blockIdx.x * blockDim.x + threadIdx.x;
    if (e < EE) {
        int d = ei[EE + e];
        int pos = atomicAdd(&g_cursor[d], 1);
        g_col[pos] = ei[e];
    }
}

// ---------------- TF32 helpers ----------------
__device__ __forceinline__ float f2tf32(float x) {
    uint32_t u;
    asm("cvt.rna.tf32.f32 %0, %1;" : "=r"(u) : "f"(x));
    return __uint_as_float(u);
}

__device__ __forceinline__ void mma_tf32(float* c, const uint32_t* a, const uint32_t* b) {
    asm volatile(
        "mma.sync.aligned.m16n8k8.row.col.f32.tf32.tf32.f32 "
        "{%0,%1,%2,%3}, {%4,%5,%6,%7}, {%8,%9}, {%0,%1,%2,%3};\n"
        : "+f"(c[0]), "+f"(c[1]), "+f"(c[2]), "+f"(c[3])
        : "r"(a[0]), "r"(a[1]), "r"(a[2]), "r"(a[3]), "r"(b[0]), "r"(b[1]));
}

// ---------------- TF32 split-compensated GEMM: Y[M x BN] = A[M x 128] @ W[128 x BN] ----------------
// D = Ahi*Whi + Ahi*Wlo + Alo*Whi  (fp32-accurate)
template <int BN>
__global__ void __launch_bounds__(256) gemm_mma(
    const float* __restrict__ A, const float* __restrict__ W,
    float* __restrict__ Y, int M) {
    constexpr int BM = 128, BK = 16;
    constexpr int AP = BM + 8;   // pad for conflict-free frag loads
    constexpr int WP = BN + 8;
    constexpr int NT = BN / 2 / 8;   // n-tiles per warp (8 or 4)

    __shared__ float As_hi[BK][AP], As_lo[BK][AP];
    __shared__ float Ws_hi[BK][WP], Ws_lo[BK][WP];

    const int tid = threadIdx.x;
    const int lane = tid & 31, wid = tid >> 5;
    const int wm = wid & 3, wn = wid >> 2;   // warp tile: 32 rows x (BN/2) cols
    const int g = lane >> 2, tig = lane & 3;
    const int m_blk = blockIdx.x * BM;

    float acc[2][NT][4];
#pragma unroll
    for (int mt = 0; mt < 2; mt++)
#pragma unroll
        for (int nt = 0; nt < NT; nt++)
#pragma unroll
            for (int j = 0; j < 4; j++) acc[mt][nt][j] = 0.f;

    for (int kc = 0; kc < DH; kc += BK) {
        // stage A tile (transposed [k][m]), split hi/lo
#pragma unroll
        for (int i = 0; i < 2; i++) {
            int idx = tid + i * 256;       // 512 float4 quads
            int m = idx >> 2, q = idx & 3;
            float4 v = make_float4(0.f, 0.f, 0.f, 0.f);
            if (m_blk + m < M)
                v = *(const float4*)&A[(size_t)(m_blk + m) * DH + kc + q * 4];
            float h0 = f2tf32(v.x), h1 = f2tf32(v.y), h2 = f2tf32(v.z), h3 = f2tf32(v.w);
            As_hi[q * 4 + 0][m] = h0;  As_lo[q * 4 + 0][m] = v.x - h0;
            As_hi[q * 4 + 1][m] = h1;  As_lo[q * 4 + 1][m] = v.y - h1;
            As_hi[q * 4 + 2][m] = h2;  As_lo[q * 4 + 2][m] = v.z - h2;
            As_hi[q * 4 + 3][m] = h3;  As_lo[q * 4 + 3][m] = v.w - h3;
        }
        // stage W tile [k][n], split hi/lo
#pragma unroll
        for (int i = 0; i < BK * BN / 4 / 256; i++) {
            int idx = tid + i * 256;
            int k = idx / (BN / 4), q = idx % (BN / 4);
            float4 v = *(const float4*)&W[(size_t)(kc + k) * BN + q * 4];
            float h0 = f2tf32(v.x), h1 = f2tf32(v.y), h2 = f2tf32(v.z), h3 = f2tf32(v.w);
            Ws_hi[k][q * 4 + 0] = h0;  Ws_lo[k][q * 4 + 0] = v.x - h0;
            Ws_hi[k][q * 4 + 1] = h1;  Ws_lo[k][q * 4 + 1] = v.y - h1;
            Ws_hi[k][q * 4 + 2] = h2;  Ws_lo[k][q * 4 + 2] = v.z - h2;
            Ws_hi[k][q * 4 + 3] = h3;  Ws_lo[k][q * 4 + 3] = v.w - h3;
        }
        __syncthreads();

#pragma unroll
        for (int ks = 0; ks < BK; ks += 8) {
            uint32_t ah[2][4], al[2][4];
#pragma unroll
            for (int mt = 0; mt < 2; mt++) {
                int r0 = wm * 32 + mt * 16 + g;
                ah[mt][0] = __float_as_uint(As_hi[ks + tig][r0]);
                ah[mt][1] = __float_as_uint(As_hi[ks + tig][r0 + 8]);
                ah[mt][2] = __float_as_uint(As_hi[ks + tig + 4][r0]);
                ah[mt][3] = __float_as_uint(As_hi[ks + tig + 4][r0 + 8]);
                al[mt][0] = __float_as_uint(As_lo[ks + tig][r0]);
                al[mt][1] = __float_as_uint(As_lo[ks + tig][r0 + 8]);
                al[mt][2] = __float_as_uint(As_lo[ks + tig + 4][r0]);
                al[mt][3] = __float_as_uint(As_lo[ks + tig + 4][r0 + 8]);
            }
#pragma unroll
            for (int nt = 0; nt < NT; nt++) {
                int n = wn * (BN / 2) + nt * 8 + g;
                uint32_t bh[2], bl[2];
                bh[0] = __float_as_uint(Ws_hi[ks + tig][n]);
                bh[1] = __float_as_uint(Ws_hi[ks + tig + 4][n]);
                bl[0] = __float_as_uint(Ws_lo[ks + tig][n]);
                bl[1] = __float_as_uint(Ws_lo[ks + tig + 4][n]);
#pragma unroll
                for (int mt = 0; mt < 2; mt++) {
                    mma_tf32(acc[mt][nt], ah[mt], bh);
                    mma_tf32(acc[mt][nt], ah[mt], bl);
                    mma_tf32(acc[mt][nt], al[mt], bh);
                }
            }
        }
        __syncthreads();
    }

    // epilogue
#pragma unroll
    for (int mt = 0; mt < 2; mt++) {
        int r0 = m_blk + wm * 32 + mt * 16 + g;
#pragma unroll
        for (int nt = 0; nt < NT; nt++) {
            int n = wn * (BN / 2) + nt * 8 + 2 * tig;
            if (r0 < M)
                *(float2*)&Y[(size_t)r0 * BN + n] = make_float2(acc[mt][nt][0], acc[mt][nt][1]);
            if (r0 + 8 < M)
                *(float2*)&Y[(size_t)(r0 + 8) * BN + n] = make_float2(acc[mt][nt][2], acc[mt][nt][3]);
        }
    }
}

// ---------------- aggregate + bias + self + ReLU (width 128), one warp per node ----------------
__global__ void agg_combine128(const float* __restrict__ tl, const float* __restrict__ tr,
                               const float* __restrict__ bias, float* __restrict__ out) {
    int node = (blockIdx.x * blockDim.x + threadIdx.x) >> 5;
    int lane = threadIdx.x & 31;
    if (node >= NN) return;
    int start = g_rowptr[node];
    int cnt = g_cnt[node];
    float ax = 0.f, ay = 0.f, az = 0.f, aw = 0.f;
    int j = 0;
    while (j < cnt) {
        int batch = min(cnt - j, 32);
        int s = (lane < batch) ? g_col[start + j + lane] : 0;
        for (int t = 0; t < batch; t++) {
            int sv = __shfl_sync(0xffffffffu, s, t);
            float4 v = *(const float4*)&tl[(size_t)sv * DH + lane * 4];
            ax += v.x; ay += v.y; az += v.z; aw += v.w;
        }
        j += batch;
    }
    float sc = g_deginv[node];
    float4 b = *(const float4*)&bias[lane * 4];
    float4 r = *(const float4*)&tr[(size_t)node * DH + lane * 4];
    float4 o = make_float4(fmaxf(ax * sc + b.x + r.x, 0.f),
                           fmaxf(ay * sc + b.y + r.y, 0.f),
                           fmaxf(az * sc + b.z + r.z, 0.f),
                           fmaxf(aw * sc + b.w + r.w, 0.f));
    *(float4*)&out[(size_t)node * DH + lane * 4] = o;
}

// ---------------- layer-3: aggregate (width 64) + bias + self + L2 normalize ----------------
__global__ void agg_norm64(const float* __restrict__ tl, const float* __restrict__ tr,
                           const float* __restrict__ bias, float* __restrict__ out) {
    int node = (blockIdx.x * blockDim.x + threadIdx.x) >> 5;
    int lane = threadIdx.x & 31;
    if (node >= NN) return;
    int start = g_rowptr[node];
    int cnt = g_cnt[node];
    float ax = 0.f, ay = 0.f;
    int j = 0;
    while (j < cnt) {
        int batch = min(cnt - j, 32);
        int s = (lane < batch) ? g_col[start + j + lane] : 0;
        for (int t = 0; t < batch; t++) {
            int sv = __shfl_sync(0xffffffffu, s, t);
            float2 v = *(const float2*)&tl[(size_t)sv * DOUT + lane * 2];
            ax += v.x; ay += v.y;
        }
        j += batch;
    }
    float sc = g_deginv[node];
    float2 b = *(const float2*)&bias[lane * 2];
    float2 r = *(const float2*)&tr[(size_t)node * DOUT + lane * 2];
    float yx = ax * sc + b.x + r.x;
    float yy = ay * sc + b.y + r.y;
    float ss = yx * yx + yy * yy;
#pragma unroll
    for (int off = 16; off > 0; off >>= 1) ss += __shfl_xor_sync(0xffffffffu, ss, off);
    float inv = 1.0f / fmaxf(sqrtf(ss), 1e-12f);
    *(float2*)&out[(size_t)node * DOUT + lane * 2] = make_float2(yx * inv, yy * inv);
}

// ---------------- launch ----------------
extern "C" void kernel_launch(void* const* d_in, const int* in_sizes, int n_in,
                              void* d_out, int out_size) {
    const float* x   = (const float*)d_in[0];
    const int*   ei  = (const int*)d_in[1];
    const float* Wl1 = (const float*)d_in[2];
    const float* bl1 = (const float*)d_in[3];
    const float* Wr1 = (const float*)d_in[4];
    const float* Wl2 = (const float*)d_in[5];
    const float* bl2 = (const float*)d_in[6];
    const float* Wr2 = (const float*)d_in[7];
    const float* Wl3 = (const float*)d_in[8];
    const float* bl3 = (const float*)d_in[9];
    const float* Wr3 = (const float*)d_in[10];
    float* out = (float*)d_out;

    void *ptl, *ptr, *p1, *p2;
    cudaGetSymbolAddress(&ptl, g_tl);
    cudaGetSymbolAddress(&ptr, g_tr);
    cudaGetSymbolAddress(&p1, g_h1);
    cudaGetSymbolAddress(&p2, g_h2);
    float* tl = (float*)ptl;
    float* tr = (float*)ptr;
    float* h1 = (float*)p1;
    float* h2 = (float*)p2;

    // CSR build
    zero_cnt_kernel<<<(NN + 255) / 256, 256>>>();
    hist_kernel<<<(EE + 255) / 256, 256>>>(ei);
    bsum_kernel<<<NCHUNK, 256>>>();
    scan_bsum_kernel<<<1, 128>>>();
    emit_kernel<<<NCHUNK, 256>>>();
    fill_kernel<<<(EE + 255) / 256, 256>>>(ei);

    const int GB = (NN + 127) / 128;        // gemm blocks
    const int AB = (NN + 7) / 8;            // agg blocks (8 warps/block)

    // layer 1: transform-then-aggregate
    gemm_mma<128><<<GB, 256>>>(x, Wl1, tl, NN);
    gemm_mma<128><<<GB, 256>>>(x, Wr1, tr, NN);
    agg_combine128<<<AB, 256>>>(tl, tr, bl1, h1);
    // layer 2
    gemm_mma<128><<<GB, 256>>>(h1, Wl2, tl, NN);
    gemm_mma<128><<<GB, 256>>>(h1, Wr2, tr, NN);
    agg_combine128<<<AB, 256>>>(tl, tr, bl2, h2);
    // layer 3 (width 64) + fused L2 normalize
    gemm_mma<64><<<GB, 256>>>(h2, Wl3, tl, NN);
    gemm_mma<64><<<GB, 256>>>(h2, Wr3, tr, NN);
    agg_norm64<<<AB, 256>>>(tl, tr, bl3, out);
}

// round 3
// speedup vs baseline: 1.9298x; 1.5821x over previous
#include <cuda_runtime.h>
#include <cuda_bf16.h>
#include <math.h>
#include <stdint.h>

#define NN 100000
#define EE 1600000
#define DH 128
#define DOUT 64
#define NCHUNK 98   // ceil(NN/1024)

// ---------------- scratch (device globals) ----------------
__device__ float g_tl[(size_t)NN * DH];
__device__ float g_tr[(size_t)NN * DH];
__device__ float g_h1[(size_t)NN * DH];
__device__ float g_h2[(size_t)NN * DH];
__device__ float g_deginv[NN];
__device__ int   g_cnt[NN];
__device__ int   g_rowptr[NN];
__device__ int   g_cursor[NN];
__device__ int   g_col[EE];
__device__ int   g_bsum[128];

// ---------------- CSR build ----------------
__global__ void zero_cnt_kernel() {
    int i = blockIdx.x * blockDim.x + threadIdx.x;
    if (i < NN) g_cnt[i] = 0;
}

__global__ void hist_kernel(const int* __restrict__ ei) {
    int e = blockIdx.x * blockDim.x + threadIdx.x;
    if (e < EE) atomicAdd(&g_cnt[ei[EE + e]], 1);
}

__global__ void bsum_kernel() {
    __shared__ int sm[256];
    int b = blockIdx.x, t = threadIdx.x;
    int base = b * 1024 + t * 4;
    int s = 0;
#pragma unroll
    for (int i = 0; i < 4; i++) {
        int n = base + i;
        if (n < NN) s += g_cnt[n];
    }
    sm[t] = s;
    __syncthreads();
    for (int off = 128; off > 0; off >>= 1) {
        if (t < off) sm[t] += sm[t + off];
        __syncthreads();
    }
    if (t == 0) g_bsum[b] = sm[0];
}

__global__ void scan_bsum_kernel() {
    __shared__ int sm[128];
    int t = threadIdx.x;
    int v = (t < NCHUNK) ? g_bsum[t] : 0;
    sm[t] = v;
    __syncthreads();
    for (int off = 1; off < 128; off <<= 1) {
        int add = (t >= off) ? sm[t - off] : 0;
        __syncthreads();
        sm[t] += add;
        __syncthreads();
    }
    if (t < NCHUNK) g_bsum[t] = sm[t] - v;  // exclusive
}

__global__ void emit_kernel() {
    __shared__ int sm[256];
    int b = blockIdx.x, t = threadIdx.x;
    int n0 = b * 1024 + t * 4;
    int c[4];
    int tsum = 0;
#pragma unroll
    for (int i = 0; i < 4; i++) {
        c[i] = (n0 + i < NN) ? g_cnt[n0 + i] : 0;
        tsum += c[i];
    }
    sm[t] = tsum;
    __syncthreads();
    for (int off = 1; off < 256; off <<= 1) {
        int add = (t >= off) ? sm[t - off] : 0;
        __syncthreads();
        sm[t] += add;
        __syncthreads();
    }
    int base = g_bsum[b] + sm[t] - tsum;
#pragma unroll
    for (int i = 0; i < 4; i++) {
        int n = n0 + i;
        if (n < NN) {
            g_rowptr[n] = base;
            g_cursor[n] = base;
            g_deginv[n] = 1.0f / (float)max(c[i], 1);
            base += c[i];
        }
    }
}

__global__ void fill_kernel(const int* __restrict__ ei) {
    int e = blockIdx.x * blockDim.x + threadIdx.x;
    if (e < EE) {
        int d = ei[EE + e];
        int pos = atomicAdd(&g_cursor[d], 1);
        g_col[pos] = ei[e];
    }
}

// ---------------- bf16 split helpers ----------------
// pack k-pair (a = even k, b = odd k) into hi/lo bf16x2 words
__device__ __forceinline__ uint2 split_pair(float a, float b) {
    __nv_bfloat16 ha = __float2bfloat16_rn(a);
    __nv_bfloat16 hb = __float2bfloat16_rn(b);
    float ra = a - __bfloat162float(ha);
    float rb = b - __bfloat162float(hb);
    __nv_bfloat162 hi2;
    hi2.x = ha; hi2.y = hb;
    __nv_bfloat162 lo2 = __floats2bfloat162_rn(ra, rb);
    uint2 r;
    r.x = *reinterpret_cast<uint32_t*>(&hi2);
    r.y = *reinterpret_cast<uint32_t*>(&lo2);
    return r;
}

__device__ __forceinline__ void mma_bf16(float* c, uint32_t a0, uint32_t a1,
                                         uint32_t a2, uint32_t a3,
                                         uint32_t b0, uint32_t b1) {
    asm volatile(
        "mma.sync.aligned.m16n8k16.row.col.f32.bf16.bf16.f32 "
        "{%0,%1,%2,%3}, {%4,%5,%6,%7}, {%8,%9}, {%0,%1,%2,%3};\n"
        : "+f"(c[0]), "+f"(c[1]), "+f"(c[2]), "+f"(c[3])
        : "r"(a0), "r"(a1), "r"(a2), "r"(a3), "r"(b0), "r"(b1));
}

// ---------------- fused dual GEMM: Yl = A@Wl, Yr = A@Wr (fp32-accurate bf16x2 split) ----------------
// BM=128, BK=16 per chunk, combined N2 = 2*BNH. Warp tile 32x64.
template <int BNH>
__global__ void __launch_bounds__((BNH == 128) ? 512 : 256, 1) gemm_dual(
    const float* __restrict__ A, const float* __restrict__ Wl,
    const float* __restrict__ Wr, float* __restrict__ Yl,
    float* __restrict__ Yr, int M) {
    constexpr int N2 = 2 * BNH;
    constexpr int THREADS = (BNH == 128) ? 512 : 256;
    constexpr int AITEMS = 512 / THREADS;       // float4 quads of A per thread
    constexpr int PERROW = N2 / 4;              // B float4 quads per k2 row
    constexpr int BITEMS = (8 * PERROW) / THREADS;  // == 1
    constexpr int AP2 = 132;                    // u2 stride (word stride 264 -> bank step 8)
    constexpr int BP2 = N2 + 4;                 // 260 / 132 -> bank step 8

    __shared__ uint2 Asm[8][AP2];   // [k2][m]  .x=hi pack, .y=lo pack
    __shared__ uint2 Bsm[8][BP2];   // [k2][n]

    const int tid = threadIdx.x;
    const int lane = tid & 31, wid = tid >> 5;
    const int wm = wid & 3, wn = wid >> 2;
    const int g = lane >> 2, tig = lane & 3;
    const int m_blk = blockIdx.x * 128;

    float acc[2][8][4];
#pragma unroll
    for (int mt = 0; mt < 2; mt++)
#pragma unroll
        for (int nt = 0; nt < 8; nt++)
#pragma unroll
            for (int j = 0; j < 4; j++) acc[mt][nt][j] = 0.f;

    float4 aPre[AITEMS];
    float4 bPre0[BITEMS], bPre1[BITEMS];

    // ---- prologue: load chunk 0 ----
    {
        const int kc = 0;
#pragma unroll
        for (int i = 0; i < AITEMS; i++) {
            int idx = tid + i * THREADS;
            int m = idx >> 2, q = idx & 3;
            float4 v = make_float4(0.f, 0.f, 0.f, 0.f);
            if (m_blk + m < M) v = *(const float4*)&A[(size_t)(m_blk + m) * DH + kc + q * 4];
            aPre[i] = v;
        }
#pragma unroll
        for (int i = 0; i < BITEMS; i++) {
            int idx = tid + i * THREADS;
            int k2 = idx / PERROW, nq = idx % PERROW;
            int n0 = nq * 4;
            const float* Wp = (n0 < BNH) ? Wl : Wr;
            int col = (n0 < BNH) ? n0 : n0 - BNH;
            size_t base = (size_t)(kc + 2 * k2) * BNH + col;
            bPre0[i] = *(const float4*)&Wp[base];
            bPre1[i] = *(const float4*)&Wp[base + BNH];
        }
    }

    for (int c = 0; c < 8; c++) {
        // ---- stage regs -> smem ----
#pragma unroll
        for (int i = 0; i < AITEMS; i++) {
            int idx = tid + i * THREADS;
            int m = idx >> 2, q = idx & 3;
            Asm[2 * q][m]     = split_pair(aPre[i].x, aPre[i].y);
            Asm[2 * q + 1][m] = split_pair(aPre[i].z, aPre[i].w);
        }
#pragma unroll
        for (int i = 0; i < BITEMS; i++) {
            int idx = tid + i * THREADS;
            int k2 = idx / PERROW, nq = idx % PERROW;
            int n0 = nq * 4;
            const float* r0 = (const float*)&bPre0[i];
            const float* r1 = (const float*)&bPre1[i];
#pragma unroll
            for (int j = 0; j < 4; j++) Bsm[k2][n0 + j] = split_pair(r0[j], r1[j]);
        }
        __syncthreads();

        // ---- prefetch next chunk ----
        if (c < 7) {
            const int kc = (c + 1) * 16;
#pragma unroll
            for (int i = 0; i < AITEMS; i++) {
                int idx = tid + i * THREADS;
                int m = idx >> 2, q = idx & 3;
                float4 v = make_float4(0.f, 0.f, 0.f, 0.f);
                if (m_blk + m < M) v = *(const float4*)&A[(size_t)(m_blk + m) * DH + kc + q * 4];
                aPre[i] = v;
            }
#pragma unroll
            for (int i = 0; i < BITEMS; i++) {
                int idx = tid + i * THREADS;
                int k2 = idx / PERROW, nq = idx % PERROW;
                int n0 = nq * 4;
                const float* Wp = (n0 < BNH) ? Wl : Wr;
                int col = (n0 < BNH) ? n0 : n0 - BNH;
                size_t base = (size_t)(kc + 2 * k2) * BNH + col;
                bPre0[i] = *(const float4*)&Wp[base];
                bPre1[i] = *(const float4*)&Wp[base + BNH];
            }
        }

        // ---- mma sweep (one k16 step) ----
        uint2 af[2][4];
#pragma unroll
        for (int mt = 0; mt < 2; mt++) {
            int r0 = wm * 32 + mt * 16 + g;
            af[mt][0] = Asm[tig][r0];
            af[mt][1] = Asm[tig][r0 + 8];
            af[mt][2] = Asm[tig + 4][r0];
            af[mt][3] = Asm[tig + 4][r0 + 8];
        }
#pragma unroll
        for (int nt = 0; nt < 8; nt++) {
            int n = wn * 64 + nt * 8 + g;
            uint2 b0 = Bsm[tig][n];
            uint2 b1 = Bsm[tig + 4][n];
#pragma unroll
            for (int mt = 0; mt < 2; mt++) {
                mma_bf16(acc[mt][nt], af[mt][0].x, af[mt][1].x, af[mt][2].x, af[mt][3].x, b0.x, b1.x);  // hi*hi
                mma_bf16(acc[mt][nt], af[mt][0].x, af[mt][1].x, af[mt][2].x, af[mt][3].x, b0.y, b1.y);  // hi*lo
                mma_bf16(acc[mt][nt], af[mt][0].y, af[mt][1].y, af[mt][2].y, af[mt][3].y, b0.x, b1.x);  // lo*hi
            }
        }
        __syncthreads();
    }

    // ---- epilogue ----
#pragma unroll
    for (int mt = 0; mt < 2; mt++) {
        int r0 = m_blk + wm * 32 + mt * 16 + g;
#pragma unroll
        for (int nt = 0; nt < 8; nt++) {
            int n2 = wn * 64 + nt * 8 + 2 * tig;
            float* Y = (n2 < BNH) ? Yl : Yr;
            int colb = (n2 < BNH) ? n2 : n2 - BNH;
            if (r0 < M)
                *(float2*)&Y[(size_t)r0 * BNH + colb] = make_float2(acc[mt][nt][0], acc[mt][nt][1]);
            if (r0 + 8 < M)
                *(float2*)&Y[(size_t)(r0 + 8) * BNH + colb] = make_float2(acc[mt][nt][2], acc[mt][nt][3]);
        }
    }
}

// ---------------- aggregate + bias + self + ReLU (width 128), one warp per node, MLP=4 ----------------
__global__ void agg_combine128(const float* __restrict__ tl, const float* __restrict__ tr,
                               const float* __restrict__ bias, float* __restrict__ out) {
    int node = (blockIdx.x * blockDim.x + threadIdx.x) >> 5;
    int lane = threadIdx.x & 31;
    if (node >= NN) return;
    int start = g_rowptr[node];
    int cnt = g_cnt[node];
    float ax = 0.f, ay = 0.f, az = 0.f, aw = 0.f;
    int j = 0;
    while (j < cnt) {
        int batch = min(cnt - j, 32);
        int s = (lane < batch) ? g_col[start + j + lane] : 0;
        int t = 0;
        for (; t + 4 <= batch; t += 4) {
            int s0 = __shfl_sync(0xffffffffu, s, t);
            int s1 = __shfl_sync(0xffffffffu, s, t + 1);
            int s2 = __shfl_sync(0xffffffffu, s, t + 2);
            int s3 = __shfl_sync(0xffffffffu, s, t + 3);
            float4 v0 = *(const float4*)&tl[(size_t)s0 * DH + lane * 4];
            float4 v1 = *(const float4*)&tl[(size_t)s1 * DH + lane * 4];
            float4 v2 = *(const float4*)&tl[(size_t)s2 * DH + lane * 4];
            float4 v3 = *(const float4*)&tl[(size_t)s3 * DH + lane * 4];
            ax += v0.x + v1.x + v2.x + v3.x;
            ay += v0.y + v1.y + v2.y + v3.y;
            az += v0.z + v1.z + v2.z + v3.z;
            aw += v0.w + v1.w + v2.w + v3.w;
        }
        for (; t < batch; t++) {
            int sv = __shfl_sync(0xffffffffu, s, t);
            float4 v = *(const float4*)&tl[(size_t)sv * DH + lane * 4];
            ax += v.x; ay += v.y; az += v.z; aw += v.w;
        }
        j += batch;
    }
    float sc = g_deginv[node];
    float4 b = *(const float4*)&bias[lane * 4];
    float4 r = *(const float4*)&tr[(size_t)node * DH + lane * 4];
    float4 o = make_float4(fmaxf(ax * sc + b.x + r.x, 0.f),
                           fmaxf(ay * sc + b.y + r.y, 0.f),
                           fmaxf(az * sc + b.z + r.z, 0.f),
                           fmaxf(aw * sc + b.w + r.w, 0.f));
    *(float4*)&out[(size_t)node * DH + lane * 4] = o;
}

// ---------------- layer-3: aggregate (width 64) + bias + self + L2 normalize ----------------
__global__ void agg_norm64(const float* __restrict__ tl, const float* __restrict__ tr,
                           const float* __restrict__ bias, float* __restrict__ out) {
    int node = (blockIdx.x * blockDim.x + threadIdx.x) >> 5;
    int lane = threadIdx.x & 31;
    if (node >= NN) return;
    int start = g_rowptr[node];
    int cnt = g_cnt[node];
    float ax = 0.f, ay = 0.f;
    int j = 0;
    while (j < cnt) {
        int batch = min(cnt - j, 32);
        int s = (lane < batch) ? g_col[start + j + lane] : 0;
        int t = 0;
        for (; t + 4 <= batch; t += 4) {
            int s0 = __shfl_sync(0xffffffffu, s, t);
            int s1 = __shfl_sync(0xffffffffu, s, t + 1);
            int s2 = __shfl_sync(0xffffffffu, s, t + 2);
            int s3 = __shfl_sync(0xffffffffu, s, t + 3);
            float2 v0 = *(const float2*)&tl[(size_t)s0 * DOUT + lane * 2];
            float2 v1 = *(const float2*)&tl[(size_t)s1 * DOUT + lane * 2];
            float2 v2 = *(const float2*)&tl[(size_t)s2 * DOUT + lane * 2];
            float2 v3 = *(const float2*)&tl[(size_t)s3 * DOUT + lane * 2];
            ax += v0.x + v1.x + v2.x + v3.x;
            ay += v0.y + v1.y + v2.y + v3.y;
        }
        for (; t < batch; t++) {
            int sv = __shfl_sync(0xffffffffu, s, t);
            float2 v = *(const float2*)&tl[(size_t)sv * DOUT + lane * 2];
            ax += v.x; ay += v.y;
        }
        j += batch;
    }
    float sc = g_deginv[node];
    float2 b = *(const float2*)&bias[lane * 2];
    float2 r = *(const float2*)&tr[(size_t)node * DOUT + lane * 2];
    float yx = ax * sc + b.x + r.x;
    float yy = ay * sc + b.y + r.y;
    float ss = yx * yx + yy * yy;
#pragma unroll
    for (int off = 16; off > 0; off >>= 1) ss += __shfl_xor_sync(0xffffffffu, ss, off);
    float inv = 1.0f / fmaxf(sqrtf(ss), 1e-12f);
    *(float2*)&out[(size_t)node * DOUT + lane * 2] = make_float2(yx * inv, yy * inv);
}

// ---------------- launch ----------------
extern "C" void kernel_launch(void* const* d_in, const int* in_sizes, int n_in,
                              void* d_out, int out_size) {
    const float* x   = (const float*)d_in[0];
    const int*   ei  = (const int*)d_in[1];
    const float* Wl1 = (const float*)d_in[2];
    const float* bl1 = (const float*)d_in[3];
    const float* Wr1 = (const float*)d_in[4];
    const float* Wl2 = (const float*)d_in[5];
    const float* bl2 = (const float*)d_in[6];
    const float* Wr2 = (const float*)d_in[7];
    const float* Wl3 = (const float*)d_in[8];
    const float* bl3 = (const float*)d_in[9];
    const float* Wr3 = (const float*)d_in[10];
    float* out = (float*)d_out;

    void *ptl, *ptr, *p1, *p2;
    cudaGetSymbolAddress(&ptl, g_tl);
    cudaGetSymbolAddress(&ptr, g_tr);
    cudaGetSymbolAddress(&p1, g_h1);
    cudaGetSymbolAddress(&p2, g_h2);
    float* tl = (float*)ptl;
    float* tr = (float*)ptr;
    float* h1 = (float*)p1;
    float* h2 = (float*)p2;

    const int GB = (NN + 127) / 128;
    const int AB = (NN + 7) / 8;

    // CSR build front half (5 launches), so ncu's skip-5 lands on the L1 gemm
    zero_cnt_kernel<<<(NN + 255) / 256, 256>>>();
    hist_kernel<<<(EE + 255) / 256, 256>>>(ei);
    bsum_kernel<<<NCHUNK, 256>>>();
    scan_bsum_kernel<<<1, 128>>>();
    emit_kernel<<<NCHUNK, 256>>>();

    // layer 1 transform (launch #6 — ncu profile target)
    gemm_dual<128><<<GB, 512>>>(x, Wl1, Wr1, tl, tr, NN);
    fill_kernel<<<(EE + 255) / 256, 256>>>(ei);
    agg_combine128<<<AB, 256>>>(tl, tr, bl1, h1);
    // layer 2
    gemm_dual<128><<<GB, 512>>>(h1, Wl2, Wr2, tl, tr, NN);
    agg_combine128<<<AB, 256>>>(tl, tr, bl2, h2);
    // layer 3 (width 64) + fused L2 normalize
    gemm_dual<64><<<GB, 256>>>(h2, Wl3, Wr3, tl, tr, NN);
    agg_norm64<<<AB, 256>>>(tl, tr, bl3, out);
}